// round 11
// baseline (speedup 1.0000x reference)
#include <cuda_runtime.h>
#include <cuda_bf16.h>
#include <math.h>
#include <stdint.h>

// ---------------- problem constants ----------------
#define NB   32
#define NC   64
#define NXX  521        // 512 + 9 pad
#define NT   49         // 40 + 9 pad
#define XT   25529      // NXX*NT
#define XTP  25536      // padded row stride (multiple of 64)
#define BCN  2048       // NB*NC

// ---------------- device global scratch ----------------
__device__ float  g_v [(size_t)BCN * XTP];        // state  (b*64+c, x*49+t)
__device__ float  g_v2[(size_t)BCN * XTP];        // u2 buffer
__device__ float2 g_F [(size_t)NB * 256 * 64];    // [b][m=kx*16+kt][i]
__device__ float2 g_G [(size_t)NB * 64 * 256];    // [b][o][kx*16+kt]
__device__ float2 g_W [(size_t)4 * 256 * 4096];   // [l][m][i][o]
__device__ float2 g_TWfx[NXX * 16];               // fwd x: (cos, -sin)(2pi kx x/521), [x][kx]
__device__ float2 g_TWix[NXX * 16];               // inv x: (cos, +sin),               [x][kx]
__device__ float2 g_TWft[NT * 16];                // fwd t: (cos, -sin)(2pi kt t/49),  [t][kt]
__device__ float2 g_TWit[16 * NT];                // inv t: f*(cos, +sin), f=(kt?2:1)/(521*49), [kt][t]

__device__ __forceinline__ float gelu_exact(float v) {
    return 0.5f * v * (1.0f + erff(v * 0.70710678118654752440f));
}

// ---------------- twiddle tables (double precision on device) ----------------
__global__ void k_basis() {
    int tid = threadIdx.x;
    const double P2 = 6.283185307179586476925286766559;
    for (int i = tid; i < NT * 16; i += 256) {        // fwd t: [t][kt]
        int t = i >> 4, k = i & 15;
        double a = P2 * (double)(k * t) / 49.0;
        g_TWft[i] = make_float2((float)cos(a), (float)(-sin(a)));
    }
    for (int i = tid; i < 16 * NT; i += 256) {        // inv t: [kt][t], scaled
        int k = i / 49, t = i - k * 49;
        double a = P2 * (double)(k * t) / 49.0;
        double f = ((k == 0) ? 1.0 : 2.0) / (521.0 * 49.0);
        g_TWit[i] = make_float2((float)(f * cos(a)), (float)(f * sin(a)));
    }
    for (int i = tid; i < NXX * 16; i += 256) {       // x twiddles: [x][kx]
        int x = i >> 4, k = i & 15;
        double a = P2 * (double)((long long)k * x) / 521.0;
        float c = (float)cos(a), s = (float)sin(a);
        g_TWfx[i] = make_float2(c, -s);
        g_TWix[i] = make_float2(c,  s);
    }
}

// ---------------- spectral weight transpose: (l,i,o,kx,kt) -> [l][m][i][o] ----------------
__global__ __launch_bounds__(256) void k_wprep(const float* __restrict__ wr,
                                               const float* __restrict__ wi) {
    __shared__ float sr[64 * 66], si[64 * 66];
    int l = blockIdx.x >> 6, i = blockIdx.x & 63;
    size_t srcb = ((size_t)(l * 64 + i)) * 64 * 256;            // + o*256 + m
    size_t dstb = (size_t)l * 256 * 4096 + (size_t)i * 64;      // + m*4096 + o
    for (int m0 = 0; m0 < 256; m0 += 64) {
        __syncthreads();
        for (int f = threadIdx.x; f < 4096; f += 256) {
            int o = f >> 6, mm = f & 63;
            sr[mm * 66 + o] = wr[srcb + (size_t)o * 256 + m0 + mm];
            si[mm * 66 + o] = wi[srcb + (size_t)o * 256 + m0 + mm];
        }
        __syncthreads();
        for (int f = threadIdx.x; f < 4096; f += 256) {
            int mm = f >> 6, o = f & 63;
            g_W[dstb + (size_t)(m0 + mm) * 4096 + o] = make_float2(sr[mm * 66 + o], si[mm * 66 + o]);
        }
    }
}

// ---------------- zero the x-pad rows (needed each replay; layers overwrite them) ----------------
__global__ void k_zxpad() {
    size_t base = (size_t)blockIdx.x * XTP + 512 * 49;
    for (int i = threadIdx.x; i < 441; i += 256) g_v[base + i] = 0.0f;
}

// ---------------- fc0 lift ----------------
__global__ __launch_bounds__(256) void k_fc0(const float* __restrict__ u,
                                             const float* __restrict__ xg,
                                             const float* __restrict__ tg,
                                             const float* __restrict__ par,
                                             const float* __restrict__ w,
                                             const float* __restrict__ bias) {
    __shared__ float sw[14 * 64], sb[64], su[10], st[40], sval[64 * 40];
    __shared__ float sx, sp0, sp1;
    int bs = blockIdx.x, b = bs >> 9, tid = threadIdx.x;
    for (int i = tid; i < 14 * 64; i += 256) sw[i] = w[i];
    if (tid < 64) sb[tid] = bias[tid];
    if (tid < 10) su[tid] = u[(size_t)bs * 10 + tid];
    if (tid >= 64 && tid < 104) st[tid - 64] = tg[b * 40 + tid - 64];
    if (tid == 128) { sx = xg[bs]; sp0 = par[b * 2]; sp1 = par[b * 2 + 1]; }
    __syncthreads();
    for (int i = tid; i < 2560; i += 256) {
        int c = i / 40, tt = i - c * 40;
        float acc = sb[c] + sx * sw[12 * 64 + c] + sp0 * sw[10 * 64 + c]
                  + sp1 * sw[11 * 64 + c] + st[tt] * sw[13 * 64 + c];
#pragma unroll
        for (int j = 0; j < 10; j++) acc += su[j] * sw[j * 64 + c];
        sval[c * 40 + tt] = acc;
    }
    __syncthreads();
    int s = bs & 511;
    float* vb = g_v + (size_t)b * 64 * XTP;
    for (int i = tid; i < 64 * 49; i += 256) {
        int c = i / 49, tp = i - c * 49;
        vb[(size_t)c * XTP + s * 49 + tp] = (tp < 40) ? sval[c * 40 + tp] : 0.0f;
    }
}

// ---------------- fused forward: x-DFT (521->16) then t-DFT (49->16) ----------------
__global__ __launch_bounds__(256) void kAB() {
    __shared__ float  sv[16 * 49];        // v chunk [xl][t]
    __shared__ float2 scs[16 * 16];       // fwd-x twiddles [xl][kx]
    __shared__ float2 sX[16 * 49];        // X1 [kx][t]
    __shared__ float2 stw[49 * 16];       // fwd-t twiddles [t][kt]
    int bc = blockIdx.x, tid = threadIdx.x;
    for (int i = tid; i < 784; i += 256) stw[i] = g_TWft[i];

    int kx0 = tid >> 6;          // 0..3
    int t   = tid & 63;          // valid if < 49
    bool tv = (t < 49);
    float ar[4] = {}, ai[4] = {};
    const float* vb = g_v + (size_t)bc * XTP;

    for (int xc = 0; xc < 33; xc++) {
        int x0 = xc * 16, nx = min(16, NXX - x0);
        __syncthreads();
        for (int i = tid; i < nx * 49; i += 256) sv[i] = vb[x0 * 49 + i];
        {
            int xl = tid >> 4;
            if (xl < nx) scs[tid] = g_TWfx[(x0 + xl) * 16 + (tid & 15)];
        }
        __syncthreads();
        if (tv) {
            for (int xl = 0; xl < nx; xl++) {
                float vv = sv[xl * 49 + t];
#pragma unroll
                for (int u2_ = 0; u2_ < 4; u2_++) {
                    float2 cs = scs[xl * 16 + kx0 + 4 * u2_];
                    ar[u2_] += vv * cs.x;
                    ai[u2_] += vv * cs.y;
                }
            }
        }
    }
    __syncthreads();
    if (tv) {
#pragma unroll
        for (int u2_ = 0; u2_ < 4; u2_++)
            sX[(kx0 + 4 * u2_) * 49 + t] = make_float2(ar[u2_], ai[u2_]);
    }
    __syncthreads();
    {
        int kx = tid >> 4, kt = tid & 15;
        float fr = 0.f, fi = 0.f;
#pragma unroll 7
        for (int tt = 0; tt < 49; tt++) {
            float2 xv = sX[kx * 49 + tt];
            float2 tw = stw[tt * 16 + kt];
            fr += xv.x * tw.x - xv.y * tw.y;
            fi += xv.x * tw.y + xv.y * tw.x;
        }
        int b = bc >> 6, ch = bc & 63;
        g_F[((size_t)b * 256 + kx * 16 + kt) * 64 + ch] = make_float2(fr, fi);
    }
}

// ---------------- stage C: per-mode 64x64 complex channel mix ----------------
__global__ __launch_bounds__(64) void kC(int l) {
    __shared__ float2 sWt[4096];
    __shared__ float2 sF[64];
    int m = blockIdx.x, o = threadIdx.x;
    const float2* Wp = g_W + ((size_t)l * 256 + m) * 4096;
    for (int i = o; i < 4096; i += 64) sWt[i] = Wp[i];
    for (int b = 0; b < NB; b++) {
        __syncthreads();
        sF[o] = g_F[((size_t)b * 256 + m) * 64 + o];
        __syncthreads();
        float gr = 0.f, gi = 0.f;
#pragma unroll 8
        for (int i = 0; i < 64; i++) {
            float2 f = sF[i], w = sWt[i * 64 + o];
            gr += f.x * w.x - f.y * w.y;
            gi += f.x * w.y + f.y * w.x;
        }
        g_G[((size_t)b * 64 + o) * 256 + m] = make_float2(gr, gi);
    }
}

// ---------------- stage F: u2 pointwise conv (64x64 GEMM over positions) ----------------
__global__ __launch_bounds__(256) void kF(const float* __restrict__ wc,
                                          const float* __restrict__ wb) {
    __shared__ float svt[16 * 64];
    __shared__ float swt[16 * 65];
    int xt0 = blockIdx.x * 64, b = blockIdx.y, tid = threadIdx.x;
    int tx = tid & 15, to = tid >> 4;
    float acc[4][4] = {};
    const float* vb = g_v + (size_t)b * 64 * XTP;
    for (int c0 = 0; c0 < 64; c0 += 16) {
        __syncthreads();
        for (int f = tid; f < 1024; f += 256) {
            int cc = f >> 6, j = f & 63;
            svt[cc * 64 + j] = vb[(size_t)(c0 + cc) * XTP + xt0 + j];
        }
        for (int f = tid; f < 1024; f += 256) {
            int o = f >> 4, cc = f & 15;
            swt[cc * 65 + o] = wc[o * 64 + c0 + cc];
        }
        __syncthreads();
#pragma unroll
        for (int cc = 0; cc < 16; cc++) {
            float4 vv = *(const float4*)&svt[cc * 64 + tx * 4];
            float w0 = swt[cc * 65 + to * 4 + 0];
            float w1 = swt[cc * 65 + to * 4 + 1];
            float w2 = swt[cc * 65 + to * 4 + 2];
            float w3 = swt[cc * 65 + to * 4 + 3];
            acc[0][0] += w0 * vv.x; acc[0][1] += w0 * vv.y; acc[0][2] += w0 * vv.z; acc[0][3] += w0 * vv.w;
            acc[1][0] += w1 * vv.x; acc[1][1] += w1 * vv.y; acc[1][2] += w1 * vv.z; acc[1][3] += w1 * vv.w;
            acc[2][0] += w2 * vv.x; acc[2][1] += w2 * vv.y; acc[2][2] += w2 * vv.z; acc[2][3] += w2 * vv.w;
            acc[3][0] += w3 * vv.x; acc[3][1] += w3 * vv.y; acc[3][2] += w3 * vv.z; acc[3][3] += w3 * vv.w;
        }
    }
    bool full = (xt0 + 64 <= XT);
#pragma unroll
    for (int oq = 0; oq < 4; oq++) {
        int o = to * 4 + oq;
        float bb = wb[o];
        float* dst = g_v2 + ((size_t)b * 64 + o) * XTP + xt0 + tx * 4;
        if (full) {
            *(float4*)dst = make_float4(acc[oq][0] + bb, acc[oq][1] + bb,
                                        acc[oq][2] + bb, acc[oq][3] + bb);
        } else {
#pragma unroll
            for (int q = 0; q < 4; q++)
                if (xt0 + tx * 4 + q < XT) dst[q] = acc[oq][q] + bb;
        }
    }
}

// ---------------- fused inverse: inv-t (16->49 complex) then inv-x + u2 + gelu ----------------
__global__ __launch_bounds__(256) void kE(int dogelu) {
    __shared__ float2 sG[256];            // [kx*16+kt]
    __shared__ float2 sq[16 * 49];        // q [kx][t]
    __shared__ float2 stw[16 * 49];       // inv-t twiddles [kt][t]
    __shared__ float2 scs[16 * 16];       // inv-x twiddles [xl][kx]
    int bo = blockIdx.x, tid = threadIdx.x;
    sG[tid] = g_G[(size_t)bo * 256 + tid];
    for (int i = tid; i < 784; i += 256) stw[i] = g_TWit[i];
    __syncthreads();
    for (int j = tid; j < 784; j += 256) {
        int kx = j / 49, t = j - kx * 49;
        float qr = 0.f, qi = 0.f;
#pragma unroll
        for (int kt = 0; kt < 16; kt++) {
            float2 g = sG[kx * 16 + kt];
            float2 tw = stw[kt * 49 + t];
            qr += g.x * tw.x - g.y * tw.y;
            qi += g.x * tw.y + g.y * tw.x;
        }
        sq[j] = make_float2(qr, qi);
    }
    float* vout = g_v + (size_t)bo * XTP;
    const float* v2 = g_v2 + (size_t)bo * XTP;
    for (int xc = 0; xc < 33; xc++) {
        int x0 = xc * 16, nx = min(16, NXX - x0);
        __syncthreads();
        {
            int xl = tid >> 4;
            if (xl < nx) scs[tid] = g_TWix[(x0 + xl) * 16 + (tid & 15)];
        }
        __syncthreads();
        int lim = nx * 49;
        for (int f = tid; f < lim; f += 256) {
            int xl = f / 49, t = f - xl * 49;
            float a = 0.f;
#pragma unroll
            for (int kx = 0; kx < 16; kx++) {
                float2 q = sq[kx * 49 + t];
                float2 cs = scs[xl * 16 + kx];
                a += q.x * cs.x - q.y * cs.y;   // Re(q * e^{+i th})
            }
            int idx = x0 * 49 + f;
            float r = a + v2[idx];
            if (dogelu) r = gelu_exact(r);
            vout[idx] = r;
        }
    }
}

// ---------------- final: crop + fc1 (gelu) + fc2 ----------------
__global__ __launch_bounds__(256) void kG(const float* __restrict__ w1,
                                          const float* __restrict__ b1,
                                          const float* __restrict__ w2,
                                          const float* __restrict__ b2,
                                          float* __restrict__ out) {
    __shared__ float sv[32 * 64];
    __shared__ float sw1[32 * 128];
    __shared__ int   sbase[64];
    __shared__ float red[16 * 64];
    int p0 = blockIdx.x * 64, tid = threadIdx.x;
    if (tid < 64) {
        int p = p0 + tid;
        int b = p / 20480, rem = p - b * 20480;
        int s = rem / 40, t = rem - s * 40;
        sbase[tid] = b * 64 * XTP + s * 49 + t;
    }
    __syncthreads();
    int pt = tid & 15, jt = tid >> 4;
    float acc[4][8] = {};
    for (int k0 = 0; k0 < 64; k0 += 32) {
        __syncthreads();
        for (int f = tid; f < 2048; f += 256) {
            int kk = f >> 6, pl = f & 63;
            sv[kk * 64 + pl] = g_v[(size_t)sbase[pl] + (size_t)(k0 + kk) * XTP];
        }
        for (int f = tid; f < 4096; f += 256) {
            int kk = f >> 7, j = f & 127;
            sw1[kk * 128 + j] = w1[(k0 + kk) * 128 + j];
        }
        __syncthreads();
#pragma unroll 4
        for (int kk = 0; kk < 32; kk++) {
            float4 vv = *(const float4*)&sv[kk * 64 + pt * 4];
            const float* wp = &sw1[kk * 128 + jt * 8];
            float4 wa = *(const float4*)wp;
            float4 wb4 = *(const float4*)(wp + 4);
            float wj[8] = {wa.x, wa.y, wa.z, wa.w, wb4.x, wb4.y, wb4.z, wb4.w};
            float vp[4] = {vv.x, vv.y, vv.z, vv.w};
#pragma unroll
            for (int pq = 0; pq < 4; pq++)
#pragma unroll
                for (int jj = 0; jj < 8; jj++)
                    acc[pq][jj] += vp[pq] * wj[jj];
        }
    }
    float pr[4] = {0.f, 0.f, 0.f, 0.f};
#pragma unroll
    for (int jj = 0; jj < 8; jj++) {
        int j = jt * 8 + jj;
        float bb = b1[j], ww = w2[j];
#pragma unroll
        for (int pq = 0; pq < 4; pq++) {
            float h = acc[pq][jj] + bb;
            h = gelu_exact(h);
            pr[pq] += h * ww;
        }
    }
#pragma unroll
    for (int pq = 0; pq < 4; pq++) red[jt * 64 + pt * 4 + pq] = pr[pq];
    __syncthreads();
    if (tid < 64) {
        float a = b2[0];
#pragma unroll
        for (int j = 0; j < 16; j++) a += red[j * 64 + tid];
        out[p0 + tid] = a;
    }
}

// ---------------- launcher ----------------
extern "C" void kernel_launch(void* const* d_in, const int* in_sizes, int n_in,
                              void* d_out, int out_size) {
    (void)in_sizes; (void)n_in; (void)out_size;
    const float* u    = (const float*)d_in[0];
    const float* x    = (const float*)d_in[1];
    const float* t    = (const float*)d_in[2];
    const float* par  = (const float*)d_in[3];
    const float* fc0w = (const float*)d_in[4];
    const float* fc0b = (const float*)d_in[5];
    const float* swr  = (const float*)d_in[6];
    const float* swi  = (const float*)d_in[7];
    const float* wconv= (const float*)d_in[8];
    const float* wbias= (const float*)d_in[9];
    const float* fc1w = (const float*)d_in[10];
    const float* fc1b = (const float*)d_in[11];
    const float* fc2w = (const float*)d_in[12];
    const float* fc2b = (const float*)d_in[13];
    float* out = (float*)d_out;

    k_basis<<<1, 256>>>();
    k_wprep<<<256, 256>>>(swr, swi);
    k_zxpad<<<2048, 256>>>();
    k_fc0<<<16384, 256>>>(u, x, t, par, fc0w, fc0b);

    for (int l = 0; l < 4; l++) {
        kAB<<<2048, 256>>>();
        kC<<<256, 64>>>(l);
        kF<<<dim3(399, 32), 256>>>(wconv + l * 4096, wbias + l * 64);
        kE<<<2048, 256>>>(l < 3 ? 1 : 0);
    }
    kG<<<10240, 256>>>(fc1w, fc1b, fc2w, fc2b, out);
}

// round 12
// speedup vs baseline: 1.0184x; 1.0184x over previous
#include <cuda_runtime.h>
#include <cuda_bf16.h>
#include <math.h>
#include <stdint.h>

// ---------------- problem constants ----------------
#define NB   32
#define NC   64
#define NXX  521        // 512 + 9 pad
#define NT   49         // 40 + 9 pad
#define XT   25529      // NXX*NT
#define XTP  25536      // padded row stride (multiple of 64)
#define BCN  2048       // NB*NC

// ---------------- device global scratch ----------------
__device__ float  g_v [(size_t)BCN * XTP];        // state  (b*64+c, x*49+t)
__device__ float  g_v2[(size_t)BCN * XTP];        // u2 buffer
__device__ float2 g_F [(size_t)NB * 256 * 64];    // [b][m=kx*16+kt][i]
__device__ float2 g_G [(size_t)NB * 64 * 256];    // [b][o][kx*16+kt]
__device__ float2 g_W [(size_t)4 * 256 * 4096];   // [l][m][i][o]
__device__ float2 g_TWfx[NXX * 16];               // fwd x: (cos, -sin)(2pi kx x/521), [x][kx]
__device__ float2 g_TWix[NXX * 16];               // inv x: (cos, +sin),               [x][kx]
__device__ float2 g_TWft[NT * 16];                // fwd t: (cos, -sin)(2pi kt t/49),  [t][kt]
__device__ float2 g_TWit[16 * NT];                // inv t: f*(cos, +sin), f=(kt?2:1)/(521*49), [kt][t]

__device__ __forceinline__ float gelu_exact(float v) {
    return 0.5f * v * (1.0f + erff(v * 0.70710678118654752440f));
}

// ---------------- merged setup: twiddle tables + zero x-pad rows ----------------
__global__ void k_setup() {
    int tid = threadIdx.x;
    // all blocks: zero pad rows of one bc row (graph replays re-dirty them)
    size_t base = (size_t)blockIdx.x * XTP + 512 * 49;
    for (int i = tid; i < 441; i += 256) g_v[base + i] = 0.0f;
    // block 0: rebuild twiddles (tiny)
    if (blockIdx.x == 0) {
        const double P2 = 6.283185307179586476925286766559;
        for (int i = tid; i < NT * 16; i += 256) {        // fwd t: [t][kt]
            int t = i >> 4, k = i & 15;
            double a = P2 * (double)(k * t) / 49.0;
            g_TWft[i] = make_float2((float)cos(a), (float)(-sin(a)));
        }
        for (int i = tid; i < 16 * NT; i += 256) {        // inv t: [kt][t], scaled
            int k = i / 49, t = i - k * 49;
            double a = P2 * (double)(k * t) / 49.0;
            double f = ((k == 0) ? 1.0 : 2.0) / (521.0 * 49.0);
            g_TWit[i] = make_float2((float)(f * cos(a)), (float)(f * sin(a)));
        }
        for (int i = tid; i < NXX * 16; i += 256) {       // x twiddles: [x][kx]
            int x = i >> 4, k = i & 15;
            double a = P2 * (double)((long long)k * x) / 521.0;
            float c = (float)cos(a), s = (float)sin(a);
            g_TWfx[i] = make_float2(c, -s);
            g_TWix[i] = make_float2(c,  s);
        }
    }
}

// ---------------- spectral weight transpose: (l,i,o,kx,kt) -> [l][m][i][o] ----------------
__global__ __launch_bounds__(256) void k_wprep(const float* __restrict__ wr,
                                               const float* __restrict__ wi) {
    __shared__ float sr[64 * 66], si[64 * 66];
    int l = blockIdx.x >> 6, i = blockIdx.x & 63;
    size_t srcb = ((size_t)(l * 64 + i)) * 64 * 256;            // + o*256 + m
    size_t dstb = (size_t)l * 256 * 4096 + (size_t)i * 64;      // + m*4096 + o
    for (int m0 = 0; m0 < 256; m0 += 64) {
        __syncthreads();
        for (int f = threadIdx.x; f < 4096; f += 256) {
            int o = f >> 6, mm = f & 63;
            sr[mm * 66 + o] = wr[srcb + (size_t)o * 256 + m0 + mm];
            si[mm * 66 + o] = wi[srcb + (size_t)o * 256 + m0 + mm];
        }
        __syncthreads();
        for (int f = threadIdx.x; f < 4096; f += 256) {
            int mm = f >> 6, o = f & 63;
            g_W[dstb + (size_t)(m0 + mm) * 4096 + o] = make_float2(sr[mm * 66 + o], si[mm * 66 + o]);
        }
    }
}

// ---------------- fc0 lift ----------------
__global__ __launch_bounds__(256) void k_fc0(const float* __restrict__ u,
                                             const float* __restrict__ xg,
                                             const float* __restrict__ tg,
                                             const float* __restrict__ par,
                                             const float* __restrict__ w,
                                             const float* __restrict__ bias) {
    __shared__ float sw[14 * 64], sb[64], su[10], st[40], sval[64 * 40];
    __shared__ float sx, sp0, sp1;
    int bs = blockIdx.x, b = bs >> 9, tid = threadIdx.x;
    for (int i = tid; i < 14 * 64; i += 256) sw[i] = w[i];
    if (tid < 64) sb[tid] = bias[tid];
    if (tid < 10) su[tid] = u[(size_t)bs * 10 + tid];
    if (tid >= 64 && tid < 104) st[tid - 64] = tg[b * 40 + tid - 64];
    if (tid == 128) { sx = xg[bs]; sp0 = par[b * 2]; sp1 = par[b * 2 + 1]; }
    __syncthreads();
    for (int i = tid; i < 2560; i += 256) {
        int c = i / 40, tt = i - c * 40;
        float acc = sb[c] + sx * sw[12 * 64 + c] + sp0 * sw[10 * 64 + c]
                  + sp1 * sw[11 * 64 + c] + st[tt] * sw[13 * 64 + c];
#pragma unroll
        for (int j = 0; j < 10; j++) acc += su[j] * sw[j * 64 + c];
        sval[c * 40 + tt] = acc;
    }
    __syncthreads();
    int s = bs & 511;
    float* vb = g_v + (size_t)b * 64 * XTP;
    for (int i = tid; i < 64 * 49; i += 256) {
        int c = i / 49, tp = i - c * 49;
        vb[(size_t)c * XTP + s * 49 + tp] = (tp < 40) ? sval[c * 40 + tp] : 0.0f;
    }
}

// ---------------- fused forward: x-DFT (521->16) then t-DFT (49->16) ----------------
__global__ __launch_bounds__(256) void kAB() {
    __shared__ float  sv[16 * 49];        // v chunk [xl][t]
    __shared__ float2 scs[16 * 16];       // fwd-x twiddles [xl][kx]
    __shared__ float2 sX[16 * 49];        // X1 [kx][t]
    __shared__ float2 stw[49 * 16];       // fwd-t twiddles [t][kt]
    int bc = blockIdx.x, tid = threadIdx.x;
    for (int i = tid; i < 784; i += 256) stw[i] = g_TWft[i];

    int kx0 = tid >> 6;          // 0..3
    int t   = tid & 63;          // valid if < 49
    bool tv = (t < 49);
    float ar[4] = {}, ai[4] = {};
    const float* vb = g_v + (size_t)bc * XTP;

    for (int xc = 0; xc < 33; xc++) {
        int x0 = xc * 16, nx = min(16, NXX - x0);
        __syncthreads();
        for (int i = tid; i < nx * 49; i += 256) sv[i] = vb[x0 * 49 + i];
        {
            int xl = tid >> 4;
            if (xl < nx) scs[tid] = g_TWfx[(x0 + xl) * 16 + (tid & 15)];
        }
        __syncthreads();
        if (tv) {
            for (int xl = 0; xl < nx; xl++) {
                float vv = sv[xl * 49 + t];
#pragma unroll
                for (int u2_ = 0; u2_ < 4; u2_++) {
                    float2 cs = scs[xl * 16 + kx0 + 4 * u2_];
                    ar[u2_] += vv * cs.x;
                    ai[u2_] += vv * cs.y;
                }
            }
        }
    }
    __syncthreads();
    if (tv) {
#pragma unroll
        for (int u2_ = 0; u2_ < 4; u2_++)
            sX[(kx0 + 4 * u2_) * 49 + t] = make_float2(ar[u2_], ai[u2_]);
    }
    __syncthreads();
    {
        int kx = tid >> 4, kt = tid & 15;
        float fr = 0.f, fi = 0.f;
#pragma unroll 7
        for (int tt = 0; tt < 49; tt++) {
            float2 xv = sX[kx * 49 + tt];
            float2 tw = stw[tt * 16 + kt];
            fr += xv.x * tw.x - xv.y * tw.y;
            fi += xv.x * tw.y + xv.y * tw.x;
        }
        int b = bc >> 6, ch = bc & 63;
        g_F[((size_t)b * 256 + kx * 16 + kt) * 64 + ch] = make_float2(fr, fi);
    }
}

// ---------------- stage C: per-mode 64x64 complex channel mix ----------------
__global__ __launch_bounds__(64) void kC(int l) {
    __shared__ float2 sWt[4096];
    __shared__ float2 sF[64];
    int m = blockIdx.x, o = threadIdx.x;
    const float2* Wp = g_W + ((size_t)l * 256 + m) * 4096;
    for (int i = o; i < 4096; i += 64) sWt[i] = Wp[i];
    for (int b = 0; b < NB; b++) {
        __syncthreads();
        sF[o] = g_F[((size_t)b * 256 + m) * 64 + o];
        __syncthreads();
        float gr = 0.f, gi = 0.f;
#pragma unroll 8
        for (int i = 0; i < 64; i++) {
            float2 f = sF[i], w = sWt[i * 64 + o];
            gr += f.x * w.x - f.y * w.y;
            gi += f.x * w.y + f.y * w.x;
        }
        g_G[((size_t)b * 64 + o) * 256 + m] = make_float2(gr, gi);
    }
}

// ---------------- stage F: u2 pointwise conv, 64o x 128xt block tile, 8o x 4xt per thread ----
__global__ __launch_bounds__(256) void kF(const float* __restrict__ wc,
                                          const float* __restrict__ wb) {
    __shared__ __align__(16) float svt[16 * 128];   // [cc][xt]
    __shared__ __align__(16) float swt[16 * 64];    // [cc][o]
    int xt0 = blockIdx.x * 128, b = blockIdx.y, tid = threadIdx.x;
    int tx = tid & 31, to = tid >> 5;               // tx: 32 xt-groups, to: 8 o-groups
    float acc[8][4] = {};
    const float* vb = g_v + (size_t)b * 64 * XTP;
    for (int c0 = 0; c0 < 64; c0 += 16) {
        __syncthreads();
        for (int f = tid; f < 2048; f += 256) {
            int cc = f >> 7, j = f & 127;
            int xj = xt0 + j;
            svt[cc * 128 + j] = (xj < XTP) ? vb[(size_t)(c0 + cc) * XTP + xj] : 0.0f;
        }
        for (int f = tid; f < 1024; f += 256) {
            int o = f & 63, cc = f >> 6;
            swt[cc * 64 + o] = wc[o * 64 + c0 + cc];
        }
        __syncthreads();
#pragma unroll
        for (int cc = 0; cc < 16; cc++) {
            float4 vv  = *(const float4*)&svt[cc * 128 + tx * 4];
            float4 wa  = *(const float4*)&swt[cc * 64 + to * 8];
            float4 wb4 = *(const float4*)&swt[cc * 64 + to * 8 + 4];
            float wj[8] = {wa.x, wa.y, wa.z, wa.w, wb4.x, wb4.y, wb4.z, wb4.w};
#pragma unroll
            for (int oq = 0; oq < 8; oq++) {
                acc[oq][0] += wj[oq] * vv.x; acc[oq][1] += wj[oq] * vv.y;
                acc[oq][2] += wj[oq] * vv.z; acc[oq][3] += wj[oq] * vv.w;
            }
        }
    }
    bool full = (xt0 + 128 <= XT);
#pragma unroll
    for (int oq = 0; oq < 8; oq++) {
        int o = to * 8 + oq;
        float bb = wb[o];
        float* dst = g_v2 + ((size_t)b * 64 + o) * XTP + xt0 + tx * 4;
        if (full) {
            *(float4*)dst = make_float4(acc[oq][0] + bb, acc[oq][1] + bb,
                                        acc[oq][2] + bb, acc[oq][3] + bb);
        } else {
#pragma unroll
            for (int q = 0; q < 4; q++)
                if (xt0 + tx * 4 + q < XT) dst[q] = acc[oq][q] + bb;
        }
    }
}

// ---------------- fused inverse: inv-t then inv-x + u2 + gelu; q register-resident ----------
__global__ __launch_bounds__(256) void kE(int dogelu) {
    __shared__ float2 sG[256];                       // [kx*16+kt]
    __shared__ float2 sq[16 * 49];                   // q [kx][t]
    __shared__ float2 stw[16 * 49];                  // inv-t twiddles [kt][t]
    __shared__ __align__(16) float4 scs4[16 * 8];    // inv-x twiddles [xl][kx-pair]: (c0,s0,c1,s1)
    int bo = blockIdx.x, tid = threadIdx.x;
    sG[tid] = g_G[(size_t)bo * 256 + tid];
    for (int i = tid; i < 784; i += 256) stw[i] = g_TWit[i];
    __syncthreads();
    // inv-t: q[kx][t] = sum_kt G[kx][kt] * twit[kt][t]
    for (int j = tid; j < 784; j += 256) {
        int kx = j / 49, t = j - kx * 49;
        float qr = 0.f, qi = 0.f;
#pragma unroll
        for (int kt = 0; kt < 16; kt++) {
            float2 g = sG[kx * 16 + kt];
            float2 tw = stw[kt * 49 + t];
            qr += g.x * tw.x - g.y * tw.y;
            qi += g.x * tw.y + g.y * tw.x;
        }
        sq[j] = make_float2(qr, qi);
    }
    __syncthreads();
    // thread owns fixed t; q in registers for whole kernel
    int t = tid & 63, xg = tid >> 6;       // xg: 4 xl-groups of 4
    bool tval = (t < 49);
    float qr[16], qi[16];
    if (tval) {
#pragma unroll
        for (int kx = 0; kx < 16; kx++) {
            float2 q = sq[kx * 49 + t];
            qr[kx] = q.x; qi[kx] = q.y;
        }
    }
    float* vout = g_v + (size_t)bo * XTP;
    const float* v2 = g_v2 + (size_t)bo * XTP;
    for (int xc = 0; xc < 33; xc++) {
        int x0 = xc * 16, nx = min(16, NXX - x0);
        __syncthreads();
        if (tid < 128) {                    // load [xl][8 kx-pairs] as float4
            int xl = tid >> 3, k2 = tid & 7;
            if (xl < nx)
                scs4[tid] = *(const float4*)&g_TWix[(x0 + xl) * 16 + 2 * k2];
        }
        __syncthreads();
        if (tval) {
#pragma unroll
            for (int j = 0; j < 4; j++) {
                int xl = xg * 4 + j;
                if (xl < nx) {
                    float a = 0.f;
#pragma unroll
                    for (int kk = 0; kk < 8; kk++) {
                        float4 cs = scs4[xl * 8 + kk];
                        a += qr[2 * kk]     * cs.x - qi[2 * kk]     * cs.y;
                        a += qr[2 * kk + 1] * cs.z - qi[2 * kk + 1] * cs.w;
                    }
                    int idx = (x0 + xl) * 49 + t;
                    float r = a + v2[idx];
                    if (dogelu) r = gelu_exact(r);
                    vout[idx] = r;
                }
            }
        }
    }
}

// ---------------- final: crop + fc1 (gelu) + fc2 ----------------
__global__ __launch_bounds__(256) void kG(const float* __restrict__ w1,
                                          const float* __restrict__ b1,
                                          const float* __restrict__ w2,
                                          const float* __restrict__ b2,
                                          float* __restrict__ out) {
    __shared__ float sv[32 * 64];
    __shared__ float sw1[32 * 128];
    __shared__ int   sbase[64];
    __shared__ float red[16 * 64];
    int p0 = blockIdx.x * 64, tid = threadIdx.x;
    if (tid < 64) {
        int p = p0 + tid;
        int b = p / 20480, rem = p - b * 20480;
        int s = rem / 40, t = rem - s * 40;
        sbase[tid] = b * 64 * XTP + s * 49 + t;
    }
    __syncthreads();
    int pt = tid & 15, jt = tid >> 4;
    float acc[4][8] = {};
    for (int k0 = 0; k0 < 64; k0 += 32) {
        __syncthreads();
        for (int f = tid; f < 2048; f += 256) {
            int kk = f >> 6, pl = f & 63;
            sv[kk * 64 + pl] = g_v[(size_t)sbase[pl] + (size_t)(k0 + kk) * XTP];
        }
        for (int f = tid; f < 4096; f += 256) {
            int kk = f >> 7, j = f & 127;
            sw1[kk * 128 + j] = w1[(k0 + kk) * 128 + j];
        }
        __syncthreads();
#pragma unroll 4
        for (int kk = 0; kk < 32; kk++) {
            float4 vv = *(const float4*)&sv[kk * 64 + pt * 4];
            const float* wp = &sw1[kk * 128 + jt * 8];
            float4 wa = *(const float4*)wp;
            float4 wb4 = *(const float4*)(wp + 4);
            float wj[8] = {wa.x, wa.y, wa.z, wa.w, wb4.x, wb4.y, wb4.z, wb4.w};
            float vp[4] = {vv.x, vv.y, vv.z, vv.w};
#pragma unroll
            for (int pq = 0; pq < 4; pq++)
#pragma unroll
                for (int jj = 0; jj < 8; jj++)
                    acc[pq][jj] += vp[pq] * wj[jj];
        }
    }
    float pr[4] = {0.f, 0.f, 0.f, 0.f};
#pragma unroll
    for (int jj = 0; jj < 8; jj++) {
        int j = jt * 8 + jj;
        float bb = b1[j], ww = w2[j];
#pragma unroll
        for (int pq = 0; pq < 4; pq++) {
            float h = acc[pq][jj] + bb;
            h = gelu_exact(h);
            pr[pq] += h * ww;
        }
    }
#pragma unroll
    for (int pq = 0; pq < 4; pq++) red[jt * 64 + pt * 4 + pq] = pr[pq];
    __syncthreads();
    if (tid < 64) {
        float a = b2[0];
#pragma unroll
        for (int j = 0; j < 16; j++) a += red[j * 64 + tid];
        out[p0 + tid] = a;
    }
}

// ---------------- launcher ----------------
extern "C" void kernel_launch(void* const* d_in, const int* in_sizes, int n_in,
                              void* d_out, int out_size) {
    (void)in_sizes; (void)n_in; (void)out_size;
    const float* u    = (const float*)d_in[0];
    const float* x    = (const float*)d_in[1];
    const float* t    = (const float*)d_in[2];
    const float* par  = (const float*)d_in[3];
    const float* fc0w = (const float*)d_in[4];
    const float* fc0b = (const float*)d_in[5];
    const float* swr  = (const float*)d_in[6];
    const float* swi  = (const float*)d_in[7];
    const float* wconv= (const float*)d_in[8];
    const float* wbias= (const float*)d_in[9];
    const float* fc1w = (const float*)d_in[10];
    const float* fc1b = (const float*)d_in[11];
    const float* fc2w = (const float*)d_in[12];
    const float* fc2b = (const float*)d_in[13];
    float* out = (float*)d_out;

    k_setup<<<2048, 256>>>();
    k_wprep<<<256, 256>>>(swr, swi);
    k_fc0<<<16384, 256>>>(u, x, t, par, fc0w, fc0b);

    for (int l = 0; l < 4; l++) {
        // kF first (reads g_v only) so the first kF sits at launch position 4 for ncu
        kF<<<dim3(200, 32), 256>>>(wconv + l * 4096, wbias + l * 64);
        kAB<<<2048, 256>>>();
        kC<<<256, 64>>>(l);
        kE<<<2048, 256>>>(l < 3 ? 1 : 0);
    }
    kG<<<10240, 256>>>(fc1w, fc1b, fc2w, fc2b, out);
}

// round 16
// speedup vs baseline: 1.0457x; 1.0269x over previous
#include <cuda_runtime.h>
#include <cuda_bf16.h>
#include <math.h>
#include <stdint.h>

#define NB   32
#define NC   64
#define NXX  521
#define NT   49
#define XT   25529
#define XTP  25536
#define BCN  2048

typedef unsigned long long u64;

__device__ __forceinline__ void ffma2(u64 &d, u64 a, u64 b) {
    asm("fma.rn.f32x2 %0, %1, %2, %0;" : "+l"(d) : "l"(a), "l"(b));
}
__device__ __forceinline__ u64 pack2(float lo, float hi) {
    u64 r; asm("mov.b64 %0, {%1, %2};" : "=l"(r) : "f"(lo), "f"(hi)); return r;
}
__device__ __forceinline__ float2 unpack2(u64 v) {
    float2 r; asm("mov.b64 {%0, %1}, %2;" : "=f"(r.x), "=f"(r.y) : "l"(v)); return r;
}

__device__ float  g_v [(size_t)BCN * XTP];
__device__ float  g_v2[(size_t)BCN * XTP];
__device__ float2 g_F [(size_t)NB * 256 * 64];
__device__ float2 g_G [(size_t)NB * 64 * 256];
__device__ float2 g_W [(size_t)4 * 256 * 4096];
__device__ float2 g_TWfx[NXX * 16];
__device__ float2 g_TWix[NXX * 16];
__device__ float2 g_TWft[NT * 16];
__device__ float2 g_TWit[16 * NT];

__device__ __forceinline__ float gelu_exact(float v) {
    return 0.5f * v * (1.0f + erff(v * 0.70710678118654752440f));
}

__global__ void k_setup() {
    int tid = threadIdx.x;
    size_t base = (size_t)blockIdx.x * XTP + 512 * 49;
    for (int i = tid; i < 441; i += 256) g_v[base + i] = 0.0f;
    if (blockIdx.x == 0) {
        const double P2 = 6.283185307179586476925286766559;
        for (int i = tid; i < NT * 16; i += 256) {
            int t = i >> 4, k = i & 15;
            double a = P2 * (double)(k * t) / 49.0;
            g_TWft[i] = make_float2((float)cos(a), (float)(-sin(a)));
        }
        for (int i = tid; i < 16 * NT; i += 256) {
            int k = i / 49, t = i - k * 49;
            double a = P2 * (double)(k * t) / 49.0;
            double f = ((k == 0) ? 1.0 : 2.0) / (521.0 * 49.0);
            g_TWit[i] = make_float2((float)(f * cos(a)), (float)(f * sin(a)));
        }
        for (int i = tid; i < NXX * 16; i += 256) {
            int x = i >> 4, k = i & 15;
            double a = P2 * (double)((long long)k * x) / 521.0;
            float c = (float)cos(a), s = (float)sin(a);
            g_TWfx[i] = make_float2(c, -s);
            g_TWix[i] = make_float2(c,  s);
        }
    }
}

__global__ __launch_bounds__(256) void k_wprep(const float* __restrict__ wr,
                                               const float* __restrict__ wi) {
    __shared__ float sr[64 * 66], si[64 * 66];
    int l = blockIdx.x >> 6, i = blockIdx.x & 63;
    size_t srcb = ((size_t)(l * 64 + i)) * 64 * 256;
    size_t dstb = (size_t)l * 256 * 4096 + (size_t)i * 64;
    for (int m0 = 0; m0 < 256; m0 += 64) {
        __syncthreads();
        for (int f = threadIdx.x; f < 4096; f += 256) {
            int o = f >> 6, mm = f & 63;
            sr[mm * 66 + o] = wr[srcb + (size_t)o * 256 + m0 + mm];
            si[mm * 66 + o] = wi[srcb + (size_t)o * 256 + m0 + mm];
        }
        __syncthreads();
        for (int f = threadIdx.x; f < 4096; f += 256) {
            int mm = f >> 6, o = f & 63;
            g_W[dstb + (size_t)(m0 + mm) * 4096 + o] = make_float2(sr[mm * 66 + o], si[mm * 66 + o]);
        }
    }
}

__global__ __launch_bounds__(256) void k_fc0(const float* __restrict__ u,
                                             const float* __restrict__ xg,
                                             const float* __restrict__ tg,
                                             const float* __restrict__ par,
                                             const float* __restrict__ w,
                                             const float* __restrict__ bias) {
    __shared__ float sw[14 * 64], sb[64], su[10], st[40], sval[64 * 40];
    __shared__ float sx, sp0, sp1;
    int bs = blockIdx.x, b = bs >> 9, tid = threadIdx.x;
    for (int i = tid; i < 14 * 64; i += 256) sw[i] = w[i];
    if (tid < 64) sb[tid] = bias[tid];
    if (tid < 10) su[tid] = u[(size_t)bs * 10 + tid];
    if (tid >= 64 && tid < 104) st[tid - 64] = tg[b * 40 + tid - 64];
    if (tid == 128) { sx = xg[bs]; sp0 = par[b * 2]; sp1 = par[b * 2 + 1]; }
    __syncthreads();
    for (int i = tid; i < 2560; i += 256) {
        int c = i / 40, tt = i - c * 40;
        float acc = sb[c] + sx * sw[12 * 64 + c] + sp0 * sw[10 * 64 + c]
                  + sp1 * sw[11 * 64 + c] + st[tt] * sw[13 * 64 + c];
#pragma unroll
        for (int j = 0; j < 10; j++) acc += su[j] * sw[j * 64 + c];
        sval[c * 40 + tt] = acc;
    }
    __syncthreads();
    int s = bs & 511;
    float* vb = g_v + (size_t)b * 64 * XTP;
    for (int i = tid; i < 64 * 49; i += 256) {
        int c = i / 49, tp = i - c * 49;
        vb[(size_t)c * XTP + s * 49 + tp] = (tp < 40) ? sval[c * 40 + tp] : 0.0f;
    }
}

__global__ __launch_bounds__(256) void kAB() {
    __shared__ float  sv[16 * 49];
    __shared__ __align__(16) float2 scs[16 * 16];
    __shared__ float2 sX[16 * 49];
    __shared__ float2 stw[49 * 16];
    int bc = blockIdx.x, tid = threadIdx.x;
    for (int i = tid; i < 784; i += 256) stw[i] = g_TWft[i];

    int kx0 = (tid >> 6) * 4;
    int t   = tid & 63;
    bool tv = (t < 49);
    u64 acc[4] = {0ull, 0ull, 0ull, 0ull};
    const float* vb = g_v + (size_t)bc * XTP;

    for (int xc = 0; xc < 33; xc++) {
        int x0 = xc * 16, nx = min(16, NXX - x0);
        __syncthreads();
        for (int i = tid; i < nx * 49; i += 256) sv[i] = vb[x0 * 49 + i];
        {
            int xl = tid >> 4;
            if (xl < nx) scs[tid] = g_TWfx[(x0 + xl) * 16 + (tid & 15)];
        }
        __syncthreads();
        if (tv) {
            for (int xl = 0; xl < nx; xl++) {
                float vvf = sv[xl * 49 + t];
                u64 vp = pack2(vvf, vvf);
                const ulonglong2* cp = (const ulonglong2*)&scs[xl * 16 + kx0];
                ulonglong2 c01 = cp[0], c23 = cp[1];
                ffma2(acc[0], vp, c01.x);
                ffma2(acc[1], vp, c01.y);
                ffma2(acc[2], vp, c23.x);
                ffma2(acc[3], vp, c23.y);
            }
        }
    }
    __syncthreads();
    if (tv) {
#pragma unroll
        for (int uq = 0; uq < 4; uq++)
            *(u64*)&sX[(kx0 + uq) * 49 + t] = acc[uq];
    }
    __syncthreads();
    {
        int kx = tid >> 4, kt = tid & 15;
        float fr = 0.f, fi = 0.f;
#pragma unroll 7
        for (int tt = 0; tt < 49; tt++) {
            float2 xv = sX[kx * 49 + tt];
            float2 tw = stw[tt * 16 + kt];
            fr += xv.x * tw.x - xv.y * tw.y;
            fi += xv.x * tw.y + xv.y * tw.x;
        }
        int b = bc >> 6, ch = bc & 63;
        g_F[((size_t)b * 256 + kx * 16 + kt) * 64 + ch] = make_float2(fr, fi);
    }
}

__global__ __launch_bounds__(256) void kC(int l) {
    __shared__ float2 sWt[4096];
    __shared__ float2 sF[4 * 64];
    int m = blockIdx.x, tid = threadIdx.x;
    int o = tid & 63, bq = tid >> 6;
    const float2* Wp = g_W + ((size_t)l * 256 + m) * 4096;
    for (int i = tid; i < 4096; i += 256) sWt[i] = Wp[i];
    for (int b0 = 0; b0 < NB; b0 += 4) {
        __syncthreads();
        sF[bq * 64 + o] = g_F[((size_t)(b0 + bq) * 256 + m) * 64 + o];
        __syncthreads();
        float gr = 0.f, gi = 0.f;
#pragma unroll 8
        for (int i = 0; i < 64; i++) {
            float2 f = sF[bq * 64 + i], w = sWt[i * 64 + o];
            gr += f.x * w.x - f.y * w.y;
            gi += f.x * w.y + f.y * w.x;
        }
        g_G[((size_t)(b0 + bq) * 64 + o) * 256 + m] = make_float2(gr, gi);
    }
}

__global__ __launch_bounds__(256) void kF(const float* __restrict__ wc,
                                          const float* __restrict__ wb) {
    __shared__ __align__(16) float2 sw2[64 * 64];
    int xt0 = blockIdx.x * 128, b = blockIdx.y, tid = threadIdx.x;
    int tx = tid & 31, to = (tid >> 5) * 8;
    for (int f = tid; f < 4096; f += 256) {
        int c = f >> 6, o = f & 63;
        float w = wc[o * 64 + c];
        sw2[c * 64 + o] = make_float2(w, w);
    }
    __syncthreads();
    int xi = xt0 + tx * 4;
    bool ld_ok = (xi < XTP);
    u64 acc[8][2] = {};
    const float* vb = g_v + (size_t)b * 64 * XTP + xi;
#pragma unroll 2
    for (int c = 0; c < 64; c++) {
        ulonglong2 vv = ld_ok ? *(const ulonglong2*)(vb + (size_t)c * XTP)
                              : make_ulonglong2(0ull, 0ull);
        const ulonglong2* wp = (const ulonglong2*)&sw2[c * 64 + to];
        ulonglong2 w01 = wp[0], w23 = wp[1], w45 = wp[2], w67 = wp[3];
        ffma2(acc[0][0], w01.x, vv.x); ffma2(acc[0][1], w01.x, vv.y);
        ffma2(acc[1][0], w01.y, vv.x); ffma2(acc[1][1], w01.y, vv.y);
        ffma2(acc[2][0], w23.x, vv.x); ffma2(acc[2][1], w23.x, vv.y);
        ffma2(acc[3][0], w23.y, vv.x); ffma2(acc[3][1], w23.y, vv.y);
        ffma2(acc[4][0], w45.x, vv.x); ffma2(acc[4][1], w45.x, vv.y);
        ffma2(acc[5][0], w45.y, vv.x); ffma2(acc[5][1], w45.y, vv.y);
        ffma2(acc[6][0], w67.x, vv.x); ffma2(acc[6][1], w67.x, vv.y);
        ffma2(acc[7][0], w67.y, vv.x); ffma2(acc[7][1], w67.y, vv.y);
    }
#pragma unroll
    for (int oq = 0; oq < 8; oq++) {
        int o = to + oq;
        float bb = wb[o];
        float2 p0 = unpack2(acc[oq][0]), p1 = unpack2(acc[oq][1]);
        float* dst = g_v2 + ((size_t)b * 64 + o) * XTP + xi;
        if (xi + 3 < XT) {
            *(float4*)dst = make_float4(p0.x + bb, p0.y + bb, p1.x + bb, p1.y + bb);
        } else if (xi < XT) {
            float r[4] = {p0.x + bb, p0.y + bb, p1.x + bb, p1.y + bb};
#pragma unroll
            for (int q = 0; q < 4; q++)
                if (xi + q < XT) dst[q] = r[q];
        }
    }
}

__global__ __launch_bounds__(256) void kE(int dogelu) {
    __shared__ float2 sG[256];
    __shared__ __align__(16) float2 sq[16 * 49];
    __shared__ float2 stw[16 * 49];
    __shared__ __align__(16) float4 scs4[16 * 8];
    int bo = blockIdx.x, tid = threadIdx.x;
    sG[tid] = g_G[(size_t)bo * 256 + tid];
    for (int i = tid; i < 784; i += 256) stw[i] = g_TWit[i];
    __syncthreads();
    for (int j = tid; j < 784; j += 256) {
        int kx = j / 49, t = j - kx * 49;
        float qr = 0.f, qi = 0.f;
#pragma unroll
        for (int kt = 0; kt < 16; kt++) {
            float2 g = sG[kx * 16 + kt];
            float2 tw = stw[kt * 49 + t];
            qr += g.x * tw.x - g.y * tw.y;
            qi += g.x * tw.y + g.y * tw.x;
        }
        sq[j] = make_float2(qr, qi);
    }
    __syncthreads();
    int t = tid & 63, xg = (tid >> 6) * 4;
    bool tval = (t < 49);
    u64 qp[16];
    if (tval) {
#pragma unroll
        for (int kx = 0; kx < 16; kx++) qp[kx] = *(const u64*)&sq[kx * 49 + t];
    }
    float* vout = g_v + (size_t)bo * XTP;
    const float* v2 = g_v2 + (size_t)bo * XTP;
    for (int xc = 0; xc < 33; xc++) {
        int x0 = xc * 16, nx = min(16, NXX - x0);
        __syncthreads();
        if (tid < 128) {
            int xl = tid >> 3, k2 = tid & 7;
            if (xl < nx)
                scs4[tid] = *(const float4*)&g_TWix[(x0 + xl) * 16 + 2 * k2];
        }
        __syncthreads();
        if (tval) {
#pragma unroll
            for (int j = 0; j < 4; j++) {
                int xl = xg + j;
                if (xl < nx) {
                    u64 a0 = 0ull, a1 = 0ull;
                    const ulonglong2* cp = (const ulonglong2*)&scs4[xl * 8];
#pragma unroll
                    for (int kk = 0; kk < 8; kk++) {
                        ulonglong2 cs = cp[kk];
                        ffma2(a0, qp[2 * kk],     cs.x);
                        ffma2(a1, qp[2 * kk + 1], cs.y);
                    }
                    float2 f0 = unpack2(a0), f1 = unpack2(a1);
                    float a = (f0.x + f1.x) - (f0.y + f1.y);
                    int idx = (x0 + xl) * 49 + t;
                    float r = a + v2[idx];
                    if (dogelu) r = gelu_exact(r);
                    vout[idx] = r;
                }
            }
        }
    }
}

__global__ __launch_bounds__(256) void kG(const float* __restrict__ w1,
                                          const float* __restrict__ b1,
                                          const float* __restrict__ w2,
                                          const float* __restrict__ b2,
                                          float* __restrict__ out) {
    __shared__ __align__(16) float sv[32 * 64];
    __shared__ __align__(16) float sw1[32 * 128];
    __shared__ int   sbase[64];
    __shared__ float red[16 * 64];
    int p0 = blockIdx.x * 64, tid = threadIdx.x;
    if (tid < 64) {
        int p = p0 + tid;
        int b = p / 20480, rem = p - b * 20480;
        int s = rem / 40, t = rem - s * 40;
        sbase[tid] = b * 64 * XTP + s * 49 + t;
    }
    __syncthreads();
    int pt = tid & 15, jt = tid >> 4;
    u64 acc2[4][4] = {};
    for (int k0 = 0; k0 < 64; k0 += 32) {
        __syncthreads();
        for (int f = tid; f < 2048; f += 256) {
            int kk = f >> 6, pl = f & 63;
            sv[kk * 64 + pl] = g_v[(size_t)sbase[pl] + (size_t)(k0 + kk) * XTP];
        }
        for (int f = tid; f < 4096; f += 256) {
            int kk = f >> 7, j = f & 127;
            sw1[kk * 128 + j] = w1[(k0 + kk) * 128 + j];
        }
        __syncthreads();
#pragma unroll 4
        for (int kk = 0; kk < 32; kk++) {
            float4 vv = *(const float4*)&sv[kk * 64 + pt * 4];
            const ulonglong2* wp = (const ulonglong2*)&sw1[kk * 128 + jt * 8];
            ulonglong2 wA = wp[0], wB = wp[1];
            u64 vp0 = pack2(vv.x, vv.x), vp1 = pack2(vv.y, vv.y);
            u64 vp2 = pack2(vv.z, vv.z), vp3 = pack2(vv.w, vv.w);
            ffma2(acc2[0][0], vp0, wA.x); ffma2(acc2[0][1], vp0, wA.y);
            ffma2(acc2[0][2], vp0, wB.x); ffma2(acc2[0][3], vp0, wB.y);
            ffma2(acc2[1][0], vp1, wA.x); ffma2(acc2[1][1], vp1, wA.y);
            ffma2(acc2[1][2], vp1, wB.x); ffma2(acc2[1][3], vp1, wB.y);
            ffma2(acc2[2][0], vp2, wA.x); ffma2(acc2[2][1], vp2, wA.y);
            ffma2(acc2[2][2], vp2, wB.x); ffma2(acc2[2][3], vp2, wB.y);
            ffma2(acc2[3][0], vp3, wA.x); ffma2(acc2[3][1], vp3, wA.y);
            ffma2(acc2[3][2], vp3, wB.x); ffma2(acc2[3][3], vp3, wB.y);
        }
    }
    float pr[4] = {0.f, 0.f, 0.f, 0.f};
#pragma unroll
    for (int jj2 = 0; jj2 < 4; jj2++) {
        int j = jt * 8 + jj2 * 2;
        float bb0 = b1[j], bb1 = b1[j + 1];
        float ww0 = w2[j], ww1 = w2[j + 1];
#pragma unroll
        for (int pq = 0; pq < 4; pq++) {
            float2 h = unpack2(acc2[pq][jj2]);
            pr[pq] += gelu_exact(h.x + bb0) * ww0 + gelu_exact(h.y + bb1) * ww1;
        }
    }
#pragma unroll
    for (int pq = 0; pq < 4; pq++) red[jt * 64 + pt * 4 + pq] = pr[pq];
    __syncthreads();
    if (tid < 64) {
        float a = b2[0];
#pragma unroll
        for (int j = 0; j < 16; j++) a += red[j * 64 + tid];
        out[p0 + tid] = a;
    }
}

extern "C" void kernel_launch(void* const* d_in, const int* in_sizes, int n_in,
                              void* d_out, int out_size) {
    (void)in_sizes; (void)n_in; (void)out_size;
    const float* u    = (const float*)d_in[0];
    const float* x    = (const float*)d_in[1];
    const float* t    = (const float*)d_in[2];
    const float* par  = (const float*)d_in[3];
    const float* fc0w = (const float*)d_in[4];
    const float* fc0b = (const float*)d_in[5];
    const float* swr  = (const float*)d_in[6];
    const float* swi  = (const float*)d_in[7];
    const float* wconv= (const float*)d_in[8];
    const float* wbias= (const float*)d_in[9];
    const float* fc1w = (const float*)d_in[10];
    const float* fc1b = (const float*)d_in[11];
    const float* fc2w = (const float*)d_in[12];
    const float* fc2b = (const float*)d_in[13];
    float* out = (float*)d_out;

    k_setup<<<2048, 256>>>();
    k_wprep<<<256, 256>>>(swr, swi);
    k_fc0<<<16384, 256>>>(u, x, t, par, fc0w, fc0b);

    for (int l = 0; l < 4; l++) {
        kF<<<dim3(200, 32), 256>>>(wconv + l * 4096, wbias + l * 64);
        kAB<<<2048, 256>>>();
        kC<<<256, 256>>>(l);
        kE<<<2048, 256>>>(l < 3 ? 1 : 0);
    }
    kG<<<10240, 256>>>(fc1w, fc1b, fc2w, fc2b, out);
}